// round 9
// baseline (speedup 1.0000x reference)
#include <cuda_runtime.h>
#include <cuda_fp16.h>
#include <cstdint>

#define D_DIM 512
#define B_MAX 2048
#define T_CAP 64

// ---------------- device scratch ----------------
__device__ __half g_wfh[3 * D_DIM * D_DIM];
__device__ __half g_wsh[3 * D_DIM * D_DIM];
__device__ __half g_wgh[D_DIM * 2 * D_DIM];
__device__ float  g_gif[T_CAP * 3 * D_DIM];
__device__ float  g_gis[T_CAP * 3 * D_DIM];
__device__ float  g_zf  [B_MAX * D_DIM];
__device__ __half g_zfh [B_MAX * D_DIM];
__device__ float  g_zfn [B_MAX * D_DIM];
__device__ __half g_zfnh[B_MAX * D_DIM];
__device__ float  g_zs0 [B_MAX * D_DIM];
__device__ __half g_zs0h[B_MAX * D_DIM];
__device__ float  g_zs1 [B_MAX * D_DIM];
__device__ __half g_zs1h[B_MAX * D_DIM];
__device__ float  g_ghf[B_MAX * 3 * D_DIM];
__device__ float  g_ghs[B_MAX * 3 * D_DIM];
__device__ float  g_gpre0[B_MAX * D_DIM];
__device__ float  g_gpre1[B_MAX * D_DIM];

// ---------------- helpers ----------------
__device__ __forceinline__ float sigm(float x) { return 1.0f / (1.0f + __expf(-x)); }

__device__ __forceinline__ void mma16(float* c, const uint32_t* a, uint32_t b0, uint32_t b1) {
    asm volatile(
        "mma.sync.aligned.m16n8k16.row.col.f32.f16.f16.f32 "
        "{%0,%1,%2,%3}, {%4,%5,%6,%7}, {%8,%9}, {%0,%1,%2,%3};\n"
        : "+f"(c[0]), "+f"(c[1]), "+f"(c[2]), "+f"(c[3])
        : "r"(a[0]), "r"(a[1]), "r"(a[2]), "r"(a[3]), "r"(b0), "r"(b1));
}

__device__ __forceinline__ void cp16(void* s, const void* g) {
    uint32_t sa = (uint32_t)__cvta_generic_to_shared(s);
    asm volatile("cp.async.cg.shared.global [%0], [%1], 16;\n" :: "r"(sa), "l"(g));
}

__device__ __forceinline__ void ldsm_x4(uint32_t& r0, uint32_t& r1, uint32_t& r2, uint32_t& r3,
                                        uint32_t addr) {
    asm volatile("ldmatrix.sync.aligned.m8n8.x4.shared.b16 {%0,%1,%2,%3}, [%4];"
                 : "=r"(r0), "=r"(r1), "=r"(r2), "=r"(r3) : "r"(addr));
}

// ---------------- fp16 GEMM core: 128x256 CTA tile, 64x64 warp tiles ----------------
// 8 warps as 2(m) x 4(n). acc = 128 regs/thread; launch_bounds(256,1).
// ldmatrix fragment loads; SSTRH=72 halves (144 B rows, conflict-free LDSM).
#define CTM 128
#define CTN 256
#define KC  64
#define SSTRH 72
#define A_STAGE (CTM * SSTRH)
#define B_STAGE (CTN * SSTRH)
#define GEMM_SMEM ((A_STAGE + B_STAGE) * 2 * 2)   // 2 stages x 2 bytes = 110592

__device__ __forceinline__ void gemm_core(
    __half* hsm,
    const __half* __restrict__ A0, const __half* __restrict__ A1, int splitK, int lda,
    const __half* __restrict__ W, int ldw,
    float* __restrict__ C, int ldc, int K, int rowBase, int colBase)
{
    __half* As = hsm;
    __half* Bs = hsm + 2 * A_STAGE;
    const uint32_t a_u32 = (uint32_t)__cvta_generic_to_shared(As);
    const uint32_t b_u32 = (uint32_t)__cvta_generic_to_shared(Bs);

    const int tid = threadIdx.x, warp = tid >> 5, lane = tid & 31;
    const int wm0 = (warp & 1) * 64;     // 2 m-groups of 64
    const int wn0 = (warp >> 1) * 64;    // 4 n-groups of 64
    const int group = lane >> 2, tid4 = lane & 3;

    // ldmatrix per-lane base byte offsets (at k=0)
    const int arow = lane & 15, akofs = (lane >> 4) * 8;
    const uint32_t aoff = a_u32 + (uint32_t)(((wm0 + arow) * SSTRH + akofs) * 2);
    const int bw = (lane & 7) + ((lane >> 4) & 1) * 8;
    const int bk = ((lane >> 3) & 1) * 8;
    const uint32_t boff = b_u32 + (uint32_t)(((wn0 + bw) * SSTRH + bk) * 2);

    float acc[4][8][4];
#pragma unroll
    for (int i = 0; i < 4; i++)
#pragma unroll
        for (int j = 0; j < 8; j++)
#pragma unroll
            for (int k = 0; k < 4; k++) acc[i][j][k] = 0.0f;

    auto issue = [&](int ic, int buf) {
        const int kk = ic * KC;
        const __half* Ab; int kloc;
        if (kk < splitK) { Ab = A0; kloc = kk; }
        else             { Ab = A1; kloc = kk - splitK; }
        __half* as = As + buf * A_STAGE;
        __half* bs = Bs + buf * B_STAGE;
#pragma unroll
        for (int t = 0; t < CTM / 32; t++) {
            const int seg = tid + t * 256;
            const int r = seg >> 3, c = (seg & 7) * 8;
            cp16(as + r * SSTRH + c, Ab + (size_t)(rowBase + r) * lda + kloc + c);
        }
#pragma unroll
        for (int t = 0; t < CTN / 32; t++) {
            const int seg = tid + t * 256;
            const int r = seg >> 3, c = (seg & 7) * 8;
            cp16(bs + r * SSTRH + c, W + (size_t)(colBase + r) * ldw + kk + c);
        }
        asm volatile("cp.async.commit_group;\n" ::);
    };

    const int NK = K / KC;
    issue(0, 0);

    for (int ic = 0; ic < NK; ic++) {
        const int buf = ic & 1;
        if (ic + 1 < NK) {
            issue(ic + 1, buf ^ 1);
            asm volatile("cp.async.wait_group 1;\n" ::);
        } else {
            asm volatile("cp.async.wait_group 0;\n" ::);
        }
        __syncthreads();

        const uint32_t abuf = (uint32_t)(buf * A_STAGE * 2);
        const uint32_t bbuf = (uint32_t)(buf * B_STAGE * 2);
#pragma unroll
        for (int k16 = 0; k16 < KC / 16; k16++) {
            const uint32_t kb = (uint32_t)(k16 * 32);
            uint32_t a[4][4];
#pragma unroll
            for (int mi = 0; mi < 4; mi++)
                ldsm_x4(a[mi][0], a[mi][1], a[mi][2], a[mi][3],
                        aoff + abuf + kb + (uint32_t)(mi * 16 * SSTRH * 2));
#pragma unroll
            for (int jj = 0; jj < 4; jj++) {
                uint32_t b00, b01, b10, b11;
                ldsm_x4(b00, b01, b10, b11,
                        boff + bbuf + kb + (uint32_t)(jj * 16 * SSTRH * 2));
#pragma unroll
                for (int mi = 0; mi < 4; mi++) {
                    mma16(acc[mi][2 * jj],     a[mi], b00, b01);
                    mma16(acc[mi][2 * jj + 1], a[mi], b10, b11);
                }
            }
        }
        __syncthreads();
    }

#pragma unroll
    for (int mi = 0; mi < 4; mi++) {
        const int r0 = rowBase + wm0 + mi * 16 + group;
#pragma unroll
        for (int j = 0; j < 8; j++) {
            const int c0 = colBase + wn0 + j * 8 + tid4 * 2;
            *(float2*)&C[(size_t)r0 * ldc + c0]       = make_float2(acc[mi][j][0], acc[mi][j][1]);
            *(float2*)&C[(size_t)(r0 + 8) * ldc + c0] = make_float2(acc[mi][j][2], acc[mi][j][3]);
        }
    }
}

// hidden GEMMs: y<6 -> fast col tiles; y>=6 -> slow col tiles at (y-6+sbase)
__global__ __launch_bounds__(256, 1) void hidden_gemm(
    const __half* __restrict__ zfh, const __half* __restrict__ zsh, int sbase)
{
    extern __shared__ __half hsm[];
    const int y = blockIdx.y;
    const bool fast = (y < 6);
    const __half* A = fast ? zfh : zsh;
    const __half* W = fast ? g_wfh : g_wsh;
    float*       C  = fast ? g_ghf : g_ghs;
    const int col = fast ? y : (y - 6 + sbase);
    gemm_core(hsm, A, A, 1 << 30, D_DIM, W, D_DIM,
              C, 3 * D_DIM, D_DIM, blockIdx.x * CTM, col * CTN);
}

// gate GEMM halves: z=0 -> zfn @ Wg[:, :512]; z=1 -> zs @ Wg[:, 512:]
__global__ __launch_bounds__(256, 1) void gate_gemm(
    const __half* __restrict__ zfnh, const __half* __restrict__ zsnh)
{
    extern __shared__ __half hsm[];
    const int z = blockIdx.z;
    const __half* A = z ? zsnh : zfnh;
    const __half* W = g_wgh + (z ? D_DIM : 0);
    float*       C  = z ? g_gpre1 : g_gpre0;
    gemm_core(hsm, A, A, 1 << 30, D_DIM, W, 2 * D_DIM,
              C, D_DIM, D_DIM, blockIdx.x * CTM, blockIdx.y * CTN);
}

// ---------------- GRU elementwise (fast + optional slow via blockIdx.z) ----------------
__global__ void gru_ew2(const float* __restrict__ gif_t, const float* __restrict__ gis_t,
                        const float* __restrict__ fbhh, const float* __restrict__ sbhh,
                        const float* __restrict__ zsc,
                        float* __restrict__ zsn, __half* __restrict__ zsnh, int BD)
{
    const int slow = blockIdx.z;
    const float* gh  = slow ? g_ghs : g_ghf;
    const float* gi  = slow ? gis_t : gif_t;
    const float* bhh = slow ? sbhh : fbhh;
    const float* h   = slow ? zsc : g_zf;
    float*  ho  = slow ? zsn : g_zfn;
    __half* hoh = slow ? zsnh : g_zfnh;

    int i = (blockIdx.x * blockDim.x + threadIdx.x) * 4;
    if (i >= BD) return;
    const int b = i >> 9;
    const int j = i & (D_DIM - 1);
    const size_t base = (size_t)b * (3 * D_DIM) + j;

    float4 gA = *(const float4*)(gh + base);
    float4 gB = *(const float4*)(gh + base + D_DIM);
    float4 gC = *(const float4*)(gh + base + 2 * D_DIM);
    float4 iA = *(const float4*)(gi + j);
    float4 iB = *(const float4*)(gi + j + D_DIM);
    float4 iC = *(const float4*)(gi + j + 2 * D_DIM);
    float4 bA = *(const float4*)(bhh + j);
    float4 bB = *(const float4*)(bhh + j + D_DIM);
    float4 bC = *(const float4*)(bhh + j + 2 * D_DIM);
    float4 hv = *(const float4*)(h + i);

    float4 o;
    { float r = sigm(iA.x + gA.x + bA.x); float z = sigm(iB.x + gB.x + bB.x);
      float n = tanhf(iC.x + r * (gC.x + bC.x)); o.x = n + z * (hv.x - n); }
    { float r = sigm(iA.y + gA.y + bA.y); float z = sigm(iB.y + gB.y + bB.y);
      float n = tanhf(iC.y + r * (gC.y + bC.y)); o.y = n + z * (hv.y - n); }
    { float r = sigm(iA.z + gA.z + bA.z); float z = sigm(iB.z + gB.z + bB.z);
      float n = tanhf(iC.z + r * (gC.z + bC.z)); o.z = n + z * (hv.z - n); }
    { float r = sigm(iA.w + gA.w + bA.w); float z = sigm(iB.w + gB.w + bB.w);
      float n = tanhf(iC.w + r * (gC.w + bC.w)); o.w = n + z * (hv.w - n); }

    *(float4*)(ho + i) = o;
    *(__half2*)(hoh + i)     = make_half2(__float2half_rn(o.x), __float2half_rn(o.y));
    *(__half2*)(hoh + i + 2) = make_half2(__float2half_rn(o.z), __float2half_rn(o.w));
}

// ---------------- gate + fuse + residual + LayerNorm ----------------
__device__ __forceinline__ float block_sum_128(float v, float* red, int tid) {
#pragma unroll
    for (int o = 16; o > 0; o >>= 1) v += __shfl_xor_sync(0xffffffffu, v, o);
    if ((tid & 31) == 0) red[tid >> 5] = v;
    __syncthreads();
    v = red[0] + red[1] + red[2] + red[3];
    __syncthreads();
    return v;
}

__global__ void gate_fuse_ln(const float* __restrict__ gateb,
                             const float* __restrict__ zs,
                             const float* __restrict__ gamma, const float* __restrict__ beta,
                             float* __restrict__ out, int t, int T)
{
    __shared__ float red[4];
    const int b = blockIdx.x, tid = threadIdx.x;
    const int j = tid * 4;
    const size_t base = (size_t)b * D_DIM + j;

    float4 p0 = *(const float4*)(g_gpre0 + base);
    float4 p1 = *(const float4*)(g_gpre1 + base);
    float4 gb = *(const float4*)(gateb + j);
    float4 a  = *(const float4*)(g_zfn + base);
    float4 s  = *(const float4*)(zs + base);
    float4 ho = *(const float4*)(g_zf + base);

    float f[4];
    { float g = sigm(p0.x + p1.x + gb.x); f[0] = s.x + g * (a.x - s.x) + ho.x; }
    { float g = sigm(p0.y + p1.y + gb.y); f[1] = s.y + g * (a.y - s.y) + ho.y; }
    { float g = sigm(p0.z + p1.z + gb.z); f[2] = s.z + g * (a.z - s.z) + ho.z; }
    { float g = sigm(p0.w + p1.w + gb.w); f[3] = s.w + g * (a.w - s.w) + ho.w; }

    float sum = f[0] + f[1] + f[2] + f[3];
    sum = block_sum_128(sum, red, tid);
    const float mu = sum * (1.0f / D_DIM);

    float sq = 0.0f;
#pragma unroll
    for (int k = 0; k < 4; k++) { float d = f[k] - mu; sq += d * d; }
    sq = block_sum_128(sq, red, tid);
    const float rstd = rsqrtf(sq * (1.0f / D_DIM) + 1e-5f);

    float4 gm = *(const float4*)(gamma + j);
    float4 bt = *(const float4*)(beta + j);
    float4 y;
    y.x = (f[0] - mu) * rstd * gm.x + bt.x;
    y.y = (f[1] - mu) * rstd * gm.y + bt.y;
    y.z = (f[2] - mu) * rstd * gm.z + bt.z;
    y.w = (f[3] - mu) * rstd * gm.w + bt.w;

    *(float4*)(out + ((size_t)b * T + t) * D_DIM + j) = y;
    *(float4*)(g_zf + base) = y;
    *(__half2*)(g_zfh + base)     = make_half2(__float2half_rn(y.x), __float2half_rn(y.y));
    *(__half2*)(g_zfh + base + 2) = make_half2(__float2half_rn(y.z), __float2half_rn(y.w));
}

// ---------------- fused prologue ----------------
__global__ void prep(const float* __restrict__ z_init,
                     const float* __restrict__ emb,
                     const float* __restrict__ fwih, const float* __restrict__ fbih,
                     const float* __restrict__ swih, const float* __restrict__ sbih,
                     const float* __restrict__ fwhh, const float* __restrict__ swhh,
                     const float* __restrict__ gatew,
                     int B, int T)
{
    const int y = blockIdx.y;
    const int tid = threadIdx.x;
    const int BD = B * D_DIM;

    if (y < 3) {
        const float* src = (y == 0) ? fwhh : (y == 1) ? swhh : gatew;
        __half* dst = (y == 0) ? g_wfh : (y == 1) ? g_wsh : g_wgh;
        const int n = (y == 2) ? (D_DIM * 2 * D_DIM) : (3 * D_DIM * D_DIM);
        for (int i = (blockIdx.x * 256 + tid) * 4; i < n; i += gridDim.x * 256 * 4) {
            float4 v = *(const float4*)(src + i);
            *(__half2*)(dst + i)     = make_half2(__float2half_rn(v.x), __float2half_rn(v.y));
            *(__half2*)(dst + i + 2) = make_half2(__float2half_rn(v.z), __float2half_rn(v.w));
        }
    } else if (y == 3) {
        for (int i = (blockIdx.x * 256 + tid) * 4; i < BD; i += gridDim.x * 256 * 4) {
            float4 v = *(const float4*)(z_init + i);
            *(float4*)(g_zf + i)  = v;
            *(float4*)(g_zs0 + i) = v;
            __half2 h01 = make_half2(__float2half_rn(v.x), __float2half_rn(v.y));
            __half2 h23 = make_half2(__float2half_rn(v.z), __float2half_rn(v.w));
            *(__half2*)(g_zfh + i)      = h01;
            *(__half2*)(g_zfh + i + 2)  = h23;
            *(__half2*)(g_zs0h + i)     = h01;
            *(__half2*)(g_zs0h + i + 2) = h23;
        }
    } else {
        const int m = blockIdx.x;
        if (m >= 3 * D_DIM || tid >= T) return;
        const float* wih = (y == 4) ? fwih : swih;
        const float* bih = (y == 4) ? fbih : sbih;
        float* gi = (y == 4) ? g_gif : g_gis;
        const float4* wr = (const float4*)(wih + (size_t)m * D_DIM);
        const float4* er = (const float4*)(emb + (size_t)tid * D_DIM);
        float s = 0.0f;
        for (int k = 0; k < D_DIM / 4; k++) {
            float4 w = wr[k], e = er[k];
            s += w.x * e.x + w.y * e.y + w.z * e.z + w.w * e.w;
        }
        gi[(size_t)tid * (3 * D_DIM) + m] = s + bih[m];
    }
}

// ---------------- host driver ----------------
extern "C" void kernel_launch(void* const* d_in, const int* in_sizes, int n_in,
                              void* d_out, int out_size)
{
    const float* z_init      = (const float*)d_in[0];
    const float* step_embeds = (const float*)d_in[1];
    const float* fast_w_ih   = (const float*)d_in[2];
    const float* fast_w_hh   = (const float*)d_in[3];
    const float* fast_b_ih   = (const float*)d_in[4];
    const float* fast_b_hh   = (const float*)d_in[5];
    const float* slow_w_ih   = (const float*)d_in[6];
    const float* slow_w_hh   = (const float*)d_in[7];
    const float* slow_b_ih   = (const float*)d_in[8];
    const float* slow_b_hh   = (const float*)d_in[9];
    const float* gate_w      = (const float*)d_in[10];
    const float* gate_b      = (const float*)d_in[11];
    const float* ln_gamma    = (const float*)d_in[12];
    const float* ln_beta     = (const float*)d_in[13];
    float* out = (float*)d_out;

    const int B  = in_sizes[0] / D_DIM;
    const int T  = out_size / (B * D_DIM);
    const int BD = B * D_DIM;

    // ALL device-symbol pointers via cudaGetSymbolAddress
    __half *zfh, *zfnh, *zsAh, *zsBh;
    float *gif, *gis, *zsA, *zsB;
    cudaGetSymbolAddress((void**)&zfh,  g_zfh);
    cudaGetSymbolAddress((void**)&gif,  g_gif);
    cudaGetSymbolAddress((void**)&gis,  g_gis);
    cudaGetSymbolAddress((void**)&zfnh, g_zfnh);
    cudaGetSymbolAddress((void**)&zsA,  g_zs0);
    cudaGetSymbolAddress((void**)&zsAh, g_zs0h);
    cudaGetSymbolAddress((void**)&zsB,  g_zs1);
    cudaGetSymbolAddress((void**)&zsBh, g_zs1h);
    float*  zs[2]  = { zsA, zsB };
    __half* zsh[2] = { zsAh, zsBh };

    cudaFuncSetAttribute(hidden_gemm, cudaFuncAttributeMaxDynamicSharedMemorySize, GEMM_SMEM);
    cudaFuncSetAttribute(gate_gemm,   cudaFuncAttributeMaxDynamicSharedMemorySize, GEMM_SMEM);

    // prologue
    prep<<<dim3(3 * D_DIM, 6), 256>>>(z_init, step_embeds,
                                      fast_w_ih, fast_b_ih, slow_w_ih, slow_b_ih,
                                      fast_w_hh, slow_w_hh, gate_w, B, T);

    const int ewBlocks = (BD / 4 + 255) / 256;
    const int MT = B / CTM;      // 16 row tiles

    int cur = 0;
    for (int t = 0; t < T; t++) {
        const bool even = ((t & 1) == 0);

        // hidden GEMMs: fast (6 col tiles of 256) + slow slice (balanced)
        // t==0: all 6 slow. odd t: slow tiles [0,3) for next even step.
        // even t>=2: slow tiles [3,6).
        int nslow, sbase;
        if (t == 0)      { nslow = 6; sbase = 0; }
        else if (!even)  { nslow = (t + 1 < T) ? 3 : 0; sbase = 0; }
        else             { nslow = 3; sbase = 3; }

        {
            dim3 grid(MT, 6 + nslow, 1);
            hidden_gemm<<<grid, 256, GEMM_SMEM>>>(zfh, zsh[cur], sbase);
        }

        // GRU elementwise (fast + slow on even steps)
        const int ncur = even ? (cur ^ 1) : cur;
        {
            dim3 grid(ewBlocks, 1, even ? 2 : 1);
            gru_ew2<<<grid, 256>>>(gif + (size_t)t * 3 * D_DIM, gis + (size_t)t * 3 * D_DIM,
                                   fast_b_hh, slow_b_hh,
                                   zs[cur], zs[ncur], zsh[ncur], BD);
        }

        // gate GEMM: zfn-half every step; zs-half only when zs changed (even steps)
        {
            dim3 grid(MT, D_DIM / CTN, even ? 2 : 1);
            gate_gemm<<<grid, 256, GEMM_SMEM>>>(zfnh, zsh[ncur]);
        }

        // fuse + residual + LN (sums gpre0 + gpre1)
        gate_fuse_ln<<<B, 128>>>(gate_b, zs[ncur], ln_gamma, ln_beta, out, t, T);

        cur = ncur;
    }
}

// round 10
// speedup vs baseline: 1.2236x; 1.2236x over previous
#include <cuda_runtime.h>
#include <cuda_fp16.h>
#include <cstdint>

#define D_DIM 512
#define B_MAX 2048
#define T_CAP 64

// ---------------- device scratch ----------------
__device__ __half g_wfh[3 * D_DIM * D_DIM];
__device__ __half g_wsh[3 * D_DIM * D_DIM];
__device__ __half g_wgh[D_DIM * 2 * D_DIM];
__device__ float  g_gif[T_CAP * 3 * D_DIM];
__device__ float  g_gis[T_CAP * 3 * D_DIM];
__device__ float  g_zf  [B_MAX * D_DIM];
__device__ __half g_zfh [B_MAX * D_DIM];
__device__ float  g_zfn [B_MAX * D_DIM];
__device__ __half g_zfnh[B_MAX * D_DIM];
__device__ float  g_zs0 [B_MAX * D_DIM];
__device__ __half g_zs0h[B_MAX * D_DIM];
__device__ float  g_zs1 [B_MAX * D_DIM];
__device__ __half g_zs1h[B_MAX * D_DIM];
__device__ float  g_ghf[B_MAX * 3 * D_DIM];
__device__ float  g_ghs[B_MAX * 3 * D_DIM];
__device__ float  g_gpre0[B_MAX * D_DIM];
__device__ float  g_gpre1[B_MAX * D_DIM];

// ---------------- helpers ----------------
__device__ __forceinline__ float sigm(float x) { return 1.0f / (1.0f + __expf(-x)); }

__device__ __forceinline__ void mma16(float* c, const uint32_t* a, uint32_t b0, uint32_t b1) {
    asm volatile(
        "mma.sync.aligned.m16n8k16.row.col.f32.f16.f16.f32 "
        "{%0,%1,%2,%3}, {%4,%5,%6,%7}, {%8,%9}, {%0,%1,%2,%3};\n"
        : "+f"(c[0]), "+f"(c[1]), "+f"(c[2]), "+f"(c[3])
        : "r"(a[0]), "r"(a[1]), "r"(a[2]), "r"(a[3]), "r"(b0), "r"(b1));
}

__device__ __forceinline__ void cp16(void* s, const void* g) {
    uint32_t sa = (uint32_t)__cvta_generic_to_shared(s);
    asm volatile("cp.async.cg.shared.global [%0], [%1], 16;\n" :: "r"(sa), "l"(g));
}

__device__ __forceinline__ void ldsm_x4(uint32_t& r0, uint32_t& r1, uint32_t& r2, uint32_t& r3,
                                        uint32_t addr) {
    asm volatile("ldmatrix.sync.aligned.m8n8.x4.shared.b16 {%0,%1,%2,%3}, [%4];"
                 : "=r"(r0), "=r"(r1), "=r"(r2), "=r"(r3) : "r"(addr));
}

// ---------------- fp16 GEMM core: C[tile] = A @ W^T, fp32 accum ----------------
// R8's proven tiles + 3-stage cp.async ring + ONE __syncthreads per K-chunk.
// SSTRH=72 halves (144 B rows, conflict-free LDSM).
#define KC  64
#define NST 3
#define SSTRH 72

template<int TM_, int TN_>
__device__ __forceinline__ void gemm_core(
    __half* hsm,
    const __half* __restrict__ A, int lda,
    const __half* __restrict__ W, int ldw,
    float* __restrict__ C, int ldc, int K, int rowBase, int colBase)
{
    constexpr int A_STAGE = TM_ * SSTRH;
    constexpr int B_STAGE = TN_ * SSTRH;
    __half* As = hsm;
    __half* Bs = hsm + NST * A_STAGE;
    const uint32_t a_u32 = (uint32_t)__cvta_generic_to_shared(As);
    const uint32_t b_u32 = (uint32_t)__cvta_generic_to_shared(Bs);

    const int tid = threadIdx.x, warp = tid >> 5, lane = tid & 31;
    constexpr int MW = (TM_ == 128) ? 4 : 2;        // warps along m
    constexpr int NJ = TN_ * MW / 64;               // n8-tiles per warp
    const int wm0 = (warp % MW) * 32;
    const int wn0 = (warp / MW) * (NJ * 8);
    const int group = lane >> 2, tid4 = lane & 3;

    // ldmatrix per-lane base byte offsets (at k=0)
    const int arow = lane & 15, akofs = (lane >> 4) * 8;
    const uint32_t aoff0 = a_u32 + (uint32_t)(((wm0 + arow) * SSTRH + akofs) * 2);
    const uint32_t aoff1 = aoff0 + (uint32_t)(16 * SSTRH * 2);
    const int bw = (lane & 7) + ((lane >> 4) & 1) * 8;
    const int bk = ((lane >> 3) & 1) * 8;
    const uint32_t boff0 = b_u32 + (uint32_t)(((wn0 + bw) * SSTRH + bk) * 2);

    float acc[2][NJ][4];
#pragma unroll
    for (int i = 0; i < 2; i++)
#pragma unroll
        for (int j = 0; j < NJ; j++)
#pragma unroll
            for (int k = 0; k < 4; k++) acc[i][j][k] = 0.0f;

    auto issue = [&](int ic, int buf) {
        const int kk = ic * KC;
        __half* as = As + buf * A_STAGE;
        __half* bs = Bs + buf * B_STAGE;
#pragma unroll
        for (int t = 0; t < TM_ / 32; t++) {
            const int seg = tid + t * 256;
            const int r = seg >> 3, c = (seg & 7) * 8;
            cp16(as + r * SSTRH + c, A + (size_t)(rowBase + r) * lda + kk + c);
        }
#pragma unroll
        for (int t = 0; t < TN_ / 32; t++) {
            const int seg = tid + t * 256;
            const int r = seg >> 3, c = (seg & 7) * 8;
            cp16(bs + r * SSTRH + c, W + (size_t)(colBase + r) * ldw + kk + c);
        }
        asm volatile("cp.async.commit_group;\n" ::);
    };

    const int NK = K / KC;
    issue(0, 0);
    if (NK > 1) issue(1, 1);

    for (int ic = 0; ic < NK; ic++) {
        const int buf = ic % NST;
        if (ic + 1 < NK) {
            asm volatile("cp.async.wait_group 1;\n" ::);
        } else {
            asm volatile("cp.async.wait_group 0;\n" ::);
        }
        __syncthreads();   // single barrier per chunk: ring depth 3 makes the
                           // producer target (ic+2)%3 never the buffer being read.

        const uint32_t abuf = (uint32_t)(buf * A_STAGE * 2);
        const uint32_t bbuf = (uint32_t)(buf * B_STAGE * 2);
#pragma unroll
        for (int k16 = 0; k16 < KC / 16; k16++) {
            const uint32_t kb = (uint32_t)(k16 * 32);
            uint32_t a[2][4];
            ldsm_x4(a[0][0], a[0][1], a[0][2], a[0][3], aoff0 + abuf + kb);
            ldsm_x4(a[1][0], a[1][1], a[1][2], a[1][3], aoff1 + abuf + kb);
#pragma unroll
            for (int jj = 0; jj < NJ / 2; jj++) {
                uint32_t b00, b01, b10, b11;
                ldsm_x4(b00, b01, b10, b11,
                        boff0 + bbuf + kb + (uint32_t)(jj * 16 * SSTRH * 2));
                mma16(acc[0][2 * jj],     a[0], b00, b01);
                mma16(acc[1][2 * jj],     a[1], b00, b01);
                mma16(acc[0][2 * jj + 1], a[0], b10, b11);
                mma16(acc[1][2 * jj + 1], a[1], b10, b11);
            }
        }
        if (ic + 2 < NK) issue(ic + 2, (ic + 2) % NST);
    }

#pragma unroll
    for (int i = 0; i < 2; i++) {
        const int r0 = rowBase + wm0 + i * 16 + group;
#pragma unroll
        for (int j = 0; j < NJ; j++) {
            const int c0 = colBase + wn0 + j * 8 + tid4 * 2;
            *(float2*)&C[(size_t)r0 * ldc + c0]       = make_float2(acc[i][j][0], acc[i][j][1]);
            *(float2*)&C[(size_t)(r0 + 8) * ldc + c0] = make_float2(acc[i][j][2], acc[i][j][3]);
        }
    }
}

// hidden GEMMs: y<12 -> fast col tiles; y>=12 -> slow col tiles at (y-12+sbase)
#define HID_SMEM ((128 + 128) * SSTRH * 2 * NST)    // 110592 B
__global__ __launch_bounds__(256, 2) void hidden_gemm(
    const __half* __restrict__ zfh, const __half* __restrict__ zsh, int sbase)
{
    extern __shared__ __half hsm[];
    const int y = blockIdx.y;
    const bool fast = (y < 12);
    const __half* Ap = fast ? zfh : zsh;
    const __half* Wp = fast ? g_wfh : g_wsh;
    float*       Cp  = fast ? g_ghf : g_ghs;
    const int col = fast ? y : (y - 12 + sbase);
    gemm_core<128, 128>(hsm, Ap, D_DIM, Wp, D_DIM,
                        Cp, 3 * D_DIM, D_DIM, blockIdx.x * 128, col * 128);
}

// gate GEMM halves: z=0 -> zfn @ Wg[:, :512] -> gpre0 ; z=1 -> zs @ Wg[:, 512:] -> gpre1
#define GATE_SMEM ((64 + 64) * SSTRH * 2 * NST)     // 55296 B
__global__ __launch_bounds__(256, 2) void gate_gemm(
    const __half* __restrict__ zfnh, const __half* __restrict__ zsnh)
{
    extern __shared__ __half hsm[];
    const int z = blockIdx.z;
    const __half* Ap = z ? zsnh : zfnh;
    const __half* Wp = g_wgh + (z ? D_DIM : 0);
    float*       Cp  = z ? g_gpre1 : g_gpre0;
    gemm_core<64, 64>(hsm, Ap, D_DIM, Wp, 2 * D_DIM,
                      Cp, D_DIM, D_DIM, blockIdx.x * 64, blockIdx.y * 64);
}

// ---------------- GRU elementwise (fast + optional slow via blockIdx.z) ----------------
__global__ void gru_ew2(const float* __restrict__ gif_t, const float* __restrict__ gis_t,
                        const float* __restrict__ fbhh, const float* __restrict__ sbhh,
                        const float* __restrict__ zsc,
                        float* __restrict__ zsn, __half* __restrict__ zsnh, int BD)
{
    const int slow = blockIdx.z;
    const float* gh  = slow ? g_ghs : g_ghf;
    const float* gi  = slow ? gis_t : gif_t;
    const float* bhh = slow ? sbhh : fbhh;
    const float* h   = slow ? zsc : g_zf;
    float*  ho  = slow ? zsn : g_zfn;
    __half* hoh = slow ? zsnh : g_zfnh;

    int i = (blockIdx.x * blockDim.x + threadIdx.x) * 4;
    if (i >= BD) return;
    const int b = i >> 9;
    const int j = i & (D_DIM - 1);
    const size_t base = (size_t)b * (3 * D_DIM) + j;

    float4 gA = *(const float4*)(gh + base);
    float4 gB = *(const float4*)(gh + base + D_DIM);
    float4 gC = *(const float4*)(gh + base + 2 * D_DIM);
    float4 iA = *(const float4*)(gi + j);
    float4 iB = *(const float4*)(gi + j + D_DIM);
    float4 iC = *(const float4*)(gi + j + 2 * D_DIM);
    float4 bA = *(const float4*)(bhh + j);
    float4 bB = *(const float4*)(bhh + j + D_DIM);
    float4 bC = *(const float4*)(bhh + j + 2 * D_DIM);
    float4 hv = *(const float4*)(h + i);

    float4 o;
    { float r = sigm(iA.x + gA.x + bA.x); float z = sigm(iB.x + gB.x + bB.x);
      float n = tanhf(iC.x + r * (gC.x + bC.x)); o.x = n + z * (hv.x - n); }
    { float r = sigm(iA.y + gA.y + bA.y); float z = sigm(iB.y + gB.y + bB.y);
      float n = tanhf(iC.y + r * (gC.y + bC.y)); o.y = n + z * (hv.y - n); }
    { float r = sigm(iA.z + gA.z + bA.z); float z = sigm(iB.z + gB.z + bB.z);
      float n = tanhf(iC.z + r * (gC.z + bC.z)); o.z = n + z * (hv.z - n); }
    { float r = sigm(iA.w + gA.w + bA.w); float z = sigm(iB.w + gB.w + bB.w);
      float n = tanhf(iC.w + r * (gC.w + bC.w)); o.w = n + z * (hv.w - n); }

    *(float4*)(ho + i) = o;
    *(__half2*)(hoh + i)     = make_half2(__float2half_rn(o.x), __float2half_rn(o.y));
    *(__half2*)(hoh + i + 2) = make_half2(__float2half_rn(o.z), __float2half_rn(o.w));
}

// ---------------- gate + fuse + residual + LayerNorm ----------------
__device__ __forceinline__ float block_sum_128(float v, float* red, int tid) {
#pragma unroll
    for (int o = 16; o > 0; o >>= 1) v += __shfl_xor_sync(0xffffffffu, v, o);
    if ((tid & 31) == 0) red[tid >> 5] = v;
    __syncthreads();
    v = red[0] + red[1] + red[2] + red[3];
    __syncthreads();
    return v;
}

__global__ void gate_fuse_ln(const float* __restrict__ gateb,
                             const float* __restrict__ zs,
                             const float* __restrict__ gamma, const float* __restrict__ beta,
                             float* __restrict__ out, int t, int T)
{
    __shared__ float red[4];
    const int b = blockIdx.x, tid = threadIdx.x;
    const int j = tid * 4;
    const size_t base = (size_t)b * D_DIM + j;

    float4 p0 = *(const float4*)(g_gpre0 + base);
    float4 p1 = *(const float4*)(g_gpre1 + base);   // zs-half: stale on odd steps == correct
    float4 gb = *(const float4*)(gateb + j);
    float4 a  = *(const float4*)(g_zfn + base);
    float4 s  = *(const float4*)(zs + base);
    float4 ho = *(const float4*)(g_zf + base);

    float f[4];
    { float g = sigm(p0.x + p1.x + gb.x); f[0] = s.x + g * (a.x - s.x) + ho.x; }
    { float g = sigm(p0.y + p1.y + gb.y); f[1] = s.y + g * (a.y - s.y) + ho.y; }
    { float g = sigm(p0.z + p1.z + gb.z); f[2] = s.z + g * (a.z - s.z) + ho.z; }
    { float g = sigm(p0.w + p1.w + gb.w); f[3] = s.w + g * (a.w - s.w) + ho.w; }

    float sum = f[0] + f[1] + f[2] + f[3];
    sum = block_sum_128(sum, red, tid);
    const float mu = sum * (1.0f / D_DIM);

    float sq = 0.0f;
#pragma unroll
    for (int k = 0; k < 4; k++) { float d = f[k] - mu; sq += d * d; }
    sq = block_sum_128(sq, red, tid);
    const float rstd = rsqrtf(sq * (1.0f / D_DIM) + 1e-5f);

    float4 gm = *(const float4*)(gamma + j);
    float4 bt = *(const float4*)(beta + j);
    float4 y;
    y.x = (f[0] - mu) * rstd * gm.x + bt.x;
    y.y = (f[1] - mu) * rstd * gm.y + bt.y;
    y.z = (f[2] - mu) * rstd * gm.z + bt.z;
    y.w = (f[3] - mu) * rstd * gm.w + bt.w;

    *(float4*)(out + ((size_t)b * T + t) * D_DIM + j) = y;
    *(float4*)(g_zf + base) = y;
    *(__half2*)(g_zfh + base)     = make_half2(__float2half_rn(y.x), __float2half_rn(y.y));
    *(__half2*)(g_zfh + base + 2) = make_half2(__float2half_rn(y.z), __float2half_rn(y.w));
}

// ---------------- fused prologue ----------------
__global__ void prep(const float* __restrict__ z_init,
                     const float* __restrict__ emb,
                     const float* __restrict__ fwih, const float* __restrict__ fbih,
                     const float* __restrict__ swih, const float* __restrict__ sbih,
                     const float* __restrict__ fwhh, const float* __restrict__ swhh,
                     const float* __restrict__ gatew,
                     int B, int T)
{
    const int y = blockIdx.y;
    const int tid = threadIdx.x;
    const int BD = B * D_DIM;

    if (y < 3) {
        const float* src = (y == 0) ? fwhh : (y == 1) ? swhh : gatew;
        __half* dst = (y == 0) ? g_wfh : (y == 1) ? g_wsh : g_wgh;
        const int n = (y == 2) ? (D_DIM * 2 * D_DIM) : (3 * D_DIM * D_DIM);
        for (int i = (blockIdx.x * 256 + tid) * 4; i < n; i += gridDim.x * 256 * 4) {
            float4 v = *(const float4*)(src + i);
            *(__half2*)(dst + i)     = make_half2(__float2half_rn(v.x), __float2half_rn(v.y));
            *(__half2*)(dst + i + 2) = make_half2(__float2half_rn(v.z), __float2half_rn(v.w));
        }
    } else if (y == 3) {
        for (int i = (blockIdx.x * 256 + tid) * 4; i < BD; i += gridDim.x * 256 * 4) {
            float4 v = *(const float4*)(z_init + i);
            *(float4*)(g_zf + i)  = v;
            *(float4*)(g_zs0 + i) = v;
            __half2 h01 = make_half2(__float2half_rn(v.x), __float2half_rn(v.y));
            __half2 h23 = make_half2(__float2half_rn(v.z), __float2half_rn(v.w));
            *(__half2*)(g_zfh + i)      = h01;
            *(__half2*)(g_zfh + i + 2)  = h23;
            *(__half2*)(g_zs0h + i)     = h01;
            *(__half2*)(g_zs0h + i + 2) = h23;
        }
    } else {
        const int m = blockIdx.x;
        if (m >= 3 * D_DIM || tid >= T) return;
        const float* wih = (y == 4) ? fwih : swih;
        const float* bih = (y == 4) ? fbih : sbih;
        float* gi = (y == 4) ? g_gif : g_gis;
        const float4* wr = (const float4*)(wih + (size_t)m * D_DIM);
        const float4* er = (const float4*)(emb + (size_t)tid * D_DIM);
        float s = 0.0f;
        for (int k = 0; k < D_DIM / 4; k++) {
            float4 w = wr[k], e = er[k];
            s += w.x * e.x + w.y * e.y + w.z * e.z + w.w * e.w;
        }
        gi[(size_t)tid * (3 * D_DIM) + m] = s + bih[m];
    }
}

// ---------------- host driver ----------------
extern "C" void kernel_launch(void* const* d_in, const int* in_sizes, int n_in,
                              void* d_out, int out_size)
{
    const float* z_init      = (const float*)d_in[0];
    const float* step_embeds = (const float*)d_in[1];
    const float* fast_w_ih   = (const float*)d_in[2];
    const float* fast_w_hh   = (const float*)d_in[3];
    const float* fast_b_ih   = (const float*)d_in[4];
    const float* fast_b_hh   = (const float*)d_in[5];
    const float* slow_w_ih   = (const float*)d_in[6];
    const float* slow_w_hh   = (const float*)d_in[7];
    const float* slow_b_ih   = (const float*)d_in[8];
    const float* slow_b_hh   = (const float*)d_in[9];
    const float* gate_w      = (const float*)d_in[10];
    const float* gate_b      = (const float*)d_in[11];
    const float* ln_gamma    = (const float*)d_in[12];
    const float* ln_beta     = (const float*)d_in[13];
    float* out = (float*)d_out;

    const int B  = in_sizes[0] / D_DIM;
    const int T  = out_size / (B * D_DIM);
    const int BD = B * D_DIM;

    // ALL device-symbol pointers via cudaGetSymbolAddress
    __half *zfh, *zfnh, *zsAh, *zsBh;
    float *gif, *gis, *zsA, *zsB;
    cudaGetSymbolAddress((void**)&zfh,  g_zfh);
    cudaGetSymbolAddress((void**)&gif,  g_gif);
    cudaGetSymbolAddress((void**)&gis,  g_gis);
    cudaGetSymbolAddress((void**)&zfnh, g_zfnh);
    cudaGetSymbolAddress((void**)&zsA,  g_zs0);
    cudaGetSymbolAddress((void**)&zsAh, g_zs0h);
    cudaGetSymbolAddress((void**)&zsB,  g_zs1);
    cudaGetSymbolAddress((void**)&zsBh, g_zs1h);
    float*  zs[2]  = { zsA, zsB };
    __half* zsh[2] = { zsAh, zsBh };

    cudaFuncSetAttribute(hidden_gemm, cudaFuncAttributeMaxDynamicSharedMemorySize, HID_SMEM);
    cudaFuncSetAttribute(gate_gemm,   cudaFuncAttributeMaxDynamicSharedMemorySize, GATE_SMEM);

    // prologue
    prep<<<dim3(3 * D_DIM, 6), 256>>>(z_init, step_embeds,
                                      fast_w_ih, fast_b_ih, slow_w_ih, slow_b_ih,
                                      fast_w_hh, slow_w_hh, gate_w, B, T);

    const int ewBlocks = (BD / 4 + 255) / 256;
    const int MT = B / 128;      // 16 row tiles

    int cur = 0;
    for (int t = 0; t < T; t++) {
        const bool even = ((t & 1) == 0);

        // hidden GEMMs: fast (12 col tiles) + slow slice (balanced across steps)
        int nslow, sbase;
        if (t == 0)      { nslow = 12; sbase = 0; }
        else if (!even)  { nslow = (t + 1 < T) ? 6 : 0; sbase = 0; }
        else             { nslow = 6;  sbase = 6; }

        {
            dim3 grid(MT, 12 + nslow, 1);
            hidden_gemm<<<grid, 256, HID_SMEM>>>(zfh, zsh[cur], sbase);
        }

        // GRU elementwise (fast + slow on even steps)
        const int ncur = even ? (cur ^ 1) : cur;
        {
            dim3 grid(ewBlocks, 1, even ? 2 : 1);
            gru_ew2<<<grid, 256>>>(gif + (size_t)t * 3 * D_DIM, gis + (size_t)t * 3 * D_DIM,
                                   fast_b_hh, slow_b_hh,
                                   zs[cur], zs[ncur], zsh[ncur], BD);
        }

        // gate GEMM: zfn-half every step; zs-half only when zs changed (even steps)
        {
            dim3 grid(B / 64, D_DIM / 64, even ? 2 : 1);
            gate_gemm<<<grid, 256, GATE_SMEM>>>(zfnh, zsh[ncur]);
        }

        // fuse + residual + LN (sums gpre0 + gpre1)
        gate_fuse_ln<<<B, 128>>>(gate_b, zs[ncur], ln_gamma, ln_beta, out, t, T);

        cur = ncur;
    }
}

// round 11
// speedup vs baseline: 1.2283x; 1.0038x over previous
#include <cuda_runtime.h>
#include <cuda_fp16.h>
#include <cstdint>

#define D_DIM 512
#define B_MAX 2048
#define T_CAP 64

// ---------------- device scratch ----------------
__device__ __half g_wfh[3 * D_DIM * D_DIM];
__device__ __half g_wsh[3 * D_DIM * D_DIM];
__device__ __half g_wgh[D_DIM * 2 * D_DIM];
__device__ float  g_gif[T_CAP * 3 * D_DIM];
__device__ float  g_gis[T_CAP * 3 * D_DIM];
__device__ float  g_zf  [B_MAX * D_DIM];
__device__ __half g_zfh [B_MAX * D_DIM];
__device__ float  g_zfn [B_MAX * D_DIM];
__device__ __half g_zfnh[B_MAX * D_DIM];
__device__ float  g_zs0 [B_MAX * D_DIM];
__device__ __half g_zs0h[B_MAX * D_DIM];
__device__ float  g_zs1 [B_MAX * D_DIM];
__device__ __half g_zs1h[B_MAX * D_DIM];
__device__ float  g_ghf[B_MAX * 3 * D_DIM];
__device__ float  g_ghs[B_MAX * 3 * D_DIM];
__device__ float  g_gpre0[B_MAX * D_DIM];
__device__ float  g_gpre1[B_MAX * D_DIM];

// ---------------- helpers ----------------
__device__ __forceinline__ float sigm(float x) { return 1.0f / (1.0f + __expf(-x)); }

__device__ __forceinline__ void mma16(float* c, const uint32_t* a, uint32_t b0, uint32_t b1) {
    asm volatile(
        "mma.sync.aligned.m16n8k16.row.col.f32.f16.f16.f32 "
        "{%0,%1,%2,%3}, {%4,%5,%6,%7}, {%8,%9}, {%0,%1,%2,%3};\n"
        : "+f"(c[0]), "+f"(c[1]), "+f"(c[2]), "+f"(c[3])
        : "r"(a[0]), "r"(a[1]), "r"(a[2]), "r"(a[3]), "r"(b0), "r"(b1));
}

__device__ __forceinline__ void cp16(void* s, const void* g) {
    uint32_t sa = (uint32_t)__cvta_generic_to_shared(s);
    asm volatile("cp.async.cg.shared.global [%0], [%1], 16;\n" :: "r"(sa), "l"(g));
}

__device__ __forceinline__ void ldsm_x4(uint32_t& r0, uint32_t& r1, uint32_t& r2, uint32_t& r3,
                                        uint32_t addr) {
    asm volatile("ldmatrix.sync.aligned.m8n8.x4.shared.b16 {%0,%1,%2,%3}, [%4];"
                 : "=r"(r0), "=r"(r1), "=r"(r2), "=r"(r3) : "r"(addr));
}

// ---------------- fp16 GEMM core: C[tile] = A @ W^T, fp32 accum ----------------
// 3-stage cp.async ring, ONE __syncthreads per K-chunk, and register
// double-buffered fragments: next k16's A and next B-pair are ldsm'd BEFORE
// the current MMAs consume the live fragments (hides ldsm latency).
#define KC  64
#define NST 3
#define SSTRH 72

template<int TM_, int TN_>
__device__ __forceinline__ void gemm_core(
    __half* hsm,
    const __half* __restrict__ A, int lda,
    const __half* __restrict__ W, int ldw,
    float* __restrict__ C, int ldc, int K, int rowBase, int colBase)
{
    constexpr int A_STAGE = TM_ * SSTRH;
    constexpr int B_STAGE = TN_ * SSTRH;
    constexpr int MW  = (TM_ == 128) ? 4 : 2;       // warps along m
    constexpr int NJ  = TN_ * MW / 64;              // n8-tiles per warp
    constexpr int NJ2 = NJ / 2;                     // B ldsm.x4 per k16
    constexpr int KC16 = KC / 16;                   // 4

    __half* As = hsm;
    __half* Bs = hsm + NST * A_STAGE;
    const uint32_t a_u32 = (uint32_t)__cvta_generic_to_shared(As);
    const uint32_t b_u32 = (uint32_t)__cvta_generic_to_shared(Bs);

    const int tid = threadIdx.x, warp = tid >> 5, lane = tid & 31;
    const int wm0 = (warp % MW) * 32;
    const int wn0 = (warp / MW) * (NJ * 8);
    const int group = lane >> 2, tid4 = lane & 3;

    // ldmatrix per-lane base byte offsets (at k=0)
    const int arow = lane & 15, akofs = (lane >> 4) * 8;
    const uint32_t aoff0 = a_u32 + (uint32_t)(((wm0 + arow) * SSTRH + akofs) * 2);
    const int bw = (lane & 7) + ((lane >> 4) & 1) * 8;
    const int bk = ((lane >> 3) & 1) * 8;
    const uint32_t boff0 = b_u32 + (uint32_t)(((wn0 + bw) * SSTRH + bk) * 2);

    float acc[2][NJ][4];
#pragma unroll
    for (int i = 0; i < 2; i++)
#pragma unroll
        for (int j = 0; j < NJ; j++)
#pragma unroll
            for (int k = 0; k < 4; k++) acc[i][j][k] = 0.0f;

    auto issue = [&](int ic, int buf) {
        const int kk = ic * KC;
        __half* as = As + buf * A_STAGE;
        __half* bs = Bs + buf * B_STAGE;
#pragma unroll
        for (int t = 0; t < TM_ / 32; t++) {
            const int seg = tid + t * 256;
            const int r = seg >> 3, c = (seg & 7) * 8;
            cp16(as + r * SSTRH + c, A + (size_t)(rowBase + r) * lda + kk + c);
        }
#pragma unroll
        for (int t = 0; t < TN_ / 32; t++) {
            const int seg = tid + t * 256;
            const int r = seg >> 3, c = (seg & 7) * 8;
            cp16(bs + r * SSTRH + c, W + (size_t)(colBase + r) * ldw + kk + c);
        }
        asm volatile("cp.async.commit_group;\n" ::);
    };

    const int NK = K / KC;
    issue(0, 0);
    if (NK > 1) issue(1, 1);

    for (int ic = 0; ic < NK; ic++) {
        const int buf = ic % NST;
        if (ic + 1 < NK) {
            asm volatile("cp.async.wait_group 1;\n" ::);
        } else {
            asm volatile("cp.async.wait_group 0;\n" ::);
        }
        __syncthreads();   // single barrier per chunk (ring depth 3: producer
                           // target (ic+2)%3 is never the buffer being read)

        const uint32_t abuf = (uint32_t)(buf * A_STAGE * 2);
        const uint32_t bbuf = (uint32_t)(buf * B_STAGE * 2);

        uint32_t a[2][2][4];   // [pipe buf][m16 tile][frag]
        uint32_t bb[2][4];     // [pipe buf][frag]

        // preload k16=0 fragments
        ldsm_x4(a[0][0][0], a[0][0][1], a[0][0][2], a[0][0][3], aoff0 + abuf);
        ldsm_x4(a[0][1][0], a[0][1][1], a[0][1][2], a[0][1][3],
                aoff0 + abuf + (uint32_t)(16 * SSTRH * 2));
        ldsm_x4(bb[0][0], bb[0][1], bb[0][2], bb[0][3], boff0 + bbuf);

#pragma unroll
        for (int k16 = 0; k16 < KC16; k16++) {
            const uint32_t kb = (uint32_t)(k16 * 32);
            // prefetch next k16's A fragments before consuming current
            if (k16 + 1 < KC16) {
                const int pa = (k16 + 1) & 1;
                ldsm_x4(a[pa][0][0], a[pa][0][1], a[pa][0][2], a[pa][0][3],
                        aoff0 + abuf + kb + 32u);
                ldsm_x4(a[pa][1][0], a[pa][1][1], a[pa][1][2], a[pa][1][3],
                        aoff0 + abuf + kb + 32u + (uint32_t)(16 * SSTRH * 2));
            }
#pragma unroll
            for (int jj = 0; jj < NJ2; jj++) {
                const int g = k16 * NJ2 + jj;
                // prefetch next B pair before consuming current
                if (g + 1 < KC16 * NJ2) {
                    const int nj = (jj + 1 < NJ2) ? jj + 1 : 0;
                    const uint32_t nkb = (jj + 1 < NJ2) ? kb : kb + 32u;
                    const int pb = (g + 1) & 1;
                    ldsm_x4(bb[pb][0], bb[pb][1], bb[pb][2], bb[pb][3],
                            boff0 + bbuf + nkb + (uint32_t)(nj * 16 * SSTRH * 2));
                }
                const uint32_t* av0 = a[k16 & 1][0];
                const uint32_t* av1 = a[k16 & 1][1];
                const uint32_t* bv  = bb[g & 1];
                mma16(acc[0][2 * jj],     av0, bv[0], bv[1]);
                mma16(acc[1][2 * jj],     av1, bv[0], bv[1]);
                mma16(acc[0][2 * jj + 1], av0, bv[2], bv[3]);
                mma16(acc[1][2 * jj + 1], av1, bv[2], bv[3]);
            }
        }
        if (ic + 2 < NK) issue(ic + 2, (ic + 2) % NST);
    }

#pragma unroll
    for (int i = 0; i < 2; i++) {
        const int r0 = rowBase + wm0 + i * 16 + group;
#pragma unroll
        for (int j = 0; j < NJ; j++) {
            const int c0 = colBase + wn0 + j * 8 + tid4 * 2;
            *(float2*)&C[(size_t)r0 * ldc + c0]       = make_float2(acc[i][j][0], acc[i][j][1]);
            *(float2*)&C[(size_t)(r0 + 8) * ldc + c0] = make_float2(acc[i][j][2], acc[i][j][3]);
        }
    }
}

// hidden GEMMs: y<12 -> fast col tiles; y>=12 -> slow col tiles at (y-12+sbase)
#define HID_SMEM ((128 + 128) * SSTRH * 2 * NST)    // 110592 B
__global__ __launch_bounds__(256, 2) void hidden_gemm(
    const __half* __restrict__ zfh, const __half* __restrict__ zsh, int sbase)
{
    extern __shared__ __half hsm[];
    const int y = blockIdx.y;
    const bool fast = (y < 12);
    const __half* Ap = fast ? zfh : zsh;
    const __half* Wp = fast ? g_wfh : g_wsh;
    float*       Cp  = fast ? g_ghf : g_ghs;
    const int col = fast ? y : (y - 12 + sbase);
    gemm_core<128, 128>(hsm, Ap, D_DIM, Wp, D_DIM,
                        Cp, 3 * D_DIM, D_DIM, blockIdx.x * 128, col * 128);
}

// gate GEMM halves: z=0 -> zfn @ Wg[:, :512] -> gpre0 ; z=1 -> zs @ Wg[:, 512:] -> gpre1
#define GATE_SMEM ((64 + 64) * SSTRH * 2 * NST)     // 55296 B
__global__ __launch_bounds__(256, 3) void gate_gemm(
    const __half* __restrict__ zfnh, const __half* __restrict__ zsnh)
{
    extern __shared__ __half hsm[];
    const int z = blockIdx.z;
    const __half* Ap = z ? zsnh : zfnh;
    const __half* Wp = g_wgh + (z ? D_DIM : 0);
    float*       Cp  = z ? g_gpre1 : g_gpre0;
    gemm_core<64, 64>(hsm, Ap, D_DIM, Wp, 2 * D_DIM,
                      Cp, D_DIM, D_DIM, blockIdx.x * 64, blockIdx.y * 64);
}

// ---------------- GRU elementwise (fast + optional slow via blockIdx.z) ----------------
__global__ void gru_ew2(const float* __restrict__ gif_t, const float* __restrict__ gis_t,
                        const float* __restrict__ fbhh, const float* __restrict__ sbhh,
                        const float* __restrict__ zsc,
                        float* __restrict__ zsn, __half* __restrict__ zsnh, int BD)
{
    const int slow = blockIdx.z;
    const float* gh  = slow ? g_ghs : g_ghf;
    const float* gi  = slow ? gis_t : gif_t;
    const float* bhh = slow ? sbhh : fbhh;
    const float* h   = slow ? zsc : g_zf;
    float*  ho  = slow ? zsn : g_zfn;
    __half* hoh = slow ? zsnh : g_zfnh;

    int i = (blockIdx.x * blockDim.x + threadIdx.x) * 4;
    if (i >= BD) return;
    const int b = i >> 9;
    const int j = i & (D_DIM - 1);
    const size_t base = (size_t)b * (3 * D_DIM) + j;

    float4 gA = *(const float4*)(gh + base);
    float4 gB = *(const float4*)(gh + base + D_DIM);
    float4 gC = *(const float4*)(gh + base + 2 * D_DIM);
    float4 iA = *(const float4*)(gi + j);
    float4 iB = *(const float4*)(gi + j + D_DIM);
    float4 iC = *(const float4*)(gi + j + 2 * D_DIM);
    float4 bA = *(const float4*)(bhh + j);
    float4 bB = *(const float4*)(bhh + j + D_DIM);
    float4 bC = *(const float4*)(bhh + j + 2 * D_DIM);
    float4 hv = *(const float4*)(h + i);

    float4 o;
    { float r = sigm(iA.x + gA.x + bA.x); float z = sigm(iB.x + gB.x + bB.x);
      float n = tanhf(iC.x + r * (gC.x + bC.x)); o.x = n + z * (hv.x - n); }
    { float r = sigm(iA.y + gA.y + bA.y); float z = sigm(iB.y + gB.y + bB.y);
      float n = tanhf(iC.y + r * (gC.y + bC.y)); o.y = n + z * (hv.y - n); }
    { float r = sigm(iA.z + gA.z + bA.z); float z = sigm(iB.z + gB.z + bB.z);
      float n = tanhf(iC.z + r * (gC.z + bC.z)); o.z = n + z * (hv.z - n); }
    { float r = sigm(iA.w + gA.w + bA.w); float z = sigm(iB.w + gB.w + bB.w);
      float n = tanhf(iC.w + r * (gC.w + bC.w)); o.w = n + z * (hv.w - n); }

    *(float4*)(ho + i) = o;
    *(__half2*)(hoh + i)     = make_half2(__float2half_rn(o.x), __float2half_rn(o.y));
    *(__half2*)(hoh + i + 2) = make_half2(__float2half_rn(o.z), __float2half_rn(o.w));
}

// ---------------- gate + fuse + residual + LayerNorm ----------------
__device__ __forceinline__ float block_sum_128(float v, float* red, int tid) {
#pragma unroll
    for (int o = 16; o > 0; o >>= 1) v += __shfl_xor_sync(0xffffffffu, v, o);
    if ((tid & 31) == 0) red[tid >> 5] = v;
    __syncthreads();
    v = red[0] + red[1] + red[2] + red[3];
    __syncthreads();
    return v;
}

__global__ void gate_fuse_ln(const float* __restrict__ gateb,
                             const float* __restrict__ zs,
                             const float* __restrict__ gamma, const float* __restrict__ beta,
                             float* __restrict__ out, int t, int T)
{
    __shared__ float red[4];
    const int b = blockIdx.x, tid = threadIdx.x;
    const int j = tid * 4;
    const size_t base = (size_t)b * D_DIM + j;

    float4 p0 = *(const float4*)(g_gpre0 + base);
    float4 p1 = *(const float4*)(g_gpre1 + base);   // zs-half: stale on odd steps == correct
    float4 gb = *(const float4*)(gateb + j);
    float4 a  = *(const float4*)(g_zfn + base);
    float4 s  = *(const float4*)(zs + base);
    float4 ho = *(const float4*)(g_zf + base);

    float f[4];
    { float g = sigm(p0.x + p1.x + gb.x); f[0] = s.x + g * (a.x - s.x) + ho.x; }
    { float g = sigm(p0.y + p1.y + gb.y); f[1] = s.y + g * (a.y - s.y) + ho.y; }
    { float g = sigm(p0.z + p1.z + gb.z); f[2] = s.z + g * (a.z - s.z) + ho.z; }
    { float g = sigm(p0.w + p1.w + gb.w); f[3] = s.w + g * (a.w - s.w) + ho.w; }

    float sum = f[0] + f[1] + f[2] + f[3];
    sum = block_sum_128(sum, red, tid);
    const float mu = sum * (1.0f / D_DIM);

    float sq = 0.0f;
#pragma unroll
    for (int k = 0; k < 4; k++) { float d = f[k] - mu; sq += d * d; }
    sq = block_sum_128(sq, red, tid);
    const float rstd = rsqrtf(sq * (1.0f / D_DIM) + 1e-5f);

    float4 gm = *(const float4*)(gamma + j);
    float4 bt = *(const float4*)(beta + j);
    float4 y;
    y.x = (f[0] - mu) * rstd * gm.x + bt.x;
    y.y = (f[1] - mu) * rstd * gm.y + bt.y;
    y.z = (f[2] - mu) * rstd * gm.z + bt.z;
    y.w = (f[3] - mu) * rstd * gm.w + bt.w;

    *(float4*)(out + ((size_t)b * T + t) * D_DIM + j) = y;
    *(float4*)(g_zf + base) = y;
    *(__half2*)(g_zfh + base)     = make_half2(__float2half_rn(y.x), __float2half_rn(y.y));
    *(__half2*)(g_zfh + base + 2) = make_half2(__float2half_rn(y.z), __float2half_rn(y.w));
}

// ---------------- fused prologue ----------------
__global__ void prep(const float* __restrict__ z_init,
                     const float* __restrict__ emb,
                     const float* __restrict__ fwih, const float* __restrict__ fbih,
                     const float* __restrict__ swih, const float* __restrict__ sbih,
                     const float* __restrict__ fwhh, const float* __restrict__ swhh,
                     const float* __restrict__ gatew,
                     int B, int T)
{
    const int y = blockIdx.y;
    const int tid = threadIdx.x;
    const int BD = B * D_DIM;

    if (y < 3) {
        const float* src = (y == 0) ? fwhh : (y == 1) ? swhh : gatew;
        __half* dst = (y == 0) ? g_wfh : (y == 1) ? g_wsh : g_wgh;
        const int n = (y == 2) ? (D_DIM * 2 * D_DIM) : (3 * D_DIM * D_DIM);
        for (int i = (blockIdx.x * 256 + tid) * 4; i < n; i += gridDim.x * 256 * 4) {
            float4 v = *(const float4*)(src + i);
            *(__half2*)(dst + i)     = make_half2(__float2half_rn(v.x), __float2half_rn(v.y));
            *(__half2*)(dst + i + 2) = make_half2(__float2half_rn(v.z), __float2half_rn(v.w));
        }
    } else if (y == 3) {
        for (int i = (blockIdx.x * 256 + tid) * 4; i < BD; i += gridDim.x * 256 * 4) {
            float4 v = *(const float4*)(z_init + i);
            *(float4*)(g_zf + i)  = v;
            *(float4*)(g_zs0 + i) = v;
            __half2 h01 = make_half2(__float2half_rn(v.x), __float2half_rn(v.y));
            __half2 h23 = make_half2(__float2half_rn(v.z), __float2half_rn(v.w));
            *(__half2*)(g_zfh + i)      = h01;
            *(__half2*)(g_zfh + i + 2)  = h23;
            *(__half2*)(g_zs0h + i)     = h01;
            *(__half2*)(g_zs0h + i + 2) = h23;
        }
    } else {
        const int m = blockIdx.x;
        if (m >= 3 * D_DIM || tid >= T) return;
        const float* wih = (y == 4) ? fwih : swih;
        const float* bih = (y == 4) ? fbih : sbih;
        float* gi = (y == 4) ? g_gif : g_gis;
        const float4* wr = (const float4*)(wih + (size_t)m * D_DIM);
        const float4* er = (const float4*)(emb + (size_t)tid * D_DIM);
        float s = 0.0f;
        for (int k = 0; k < D_DIM / 4; k++) {
            float4 w = wr[k], e = er[k];
            s += w.x * e.x + w.y * e.y + w.z * e.z + w.w * e.w;
        }
        gi[(size_t)tid * (3 * D_DIM) + m] = s + bih[m];
    }
}

// ---------------- host driver ----------------
extern "C" void kernel_launch(void* const* d_in, const int* in_sizes, int n_in,
                              void* d_out, int out_size)
{
    const float* z_init      = (const float*)d_in[0];
    const float* step_embeds = (const float*)d_in[1];
    const float* fast_w_ih   = (const float*)d_in[2];
    const float* fast_w_hh   = (const float*)d_in[3];
    const float* fast_b_ih   = (const float*)d_in[4];
    const float* fast_b_hh   = (const float*)d_in[5];
    const float* slow_w_ih   = (const float*)d_in[6];
    const float* slow_w_hh   = (const float*)d_in[7];
    const float* slow_b_ih   = (const float*)d_in[8];
    const float* slow_b_hh   = (const float*)d_in[9];
    const float* gate_w      = (const float*)d_in[10];
    const float* gate_b      = (const float*)d_in[11];
    const float* ln_gamma    = (const float*)d_in[12];
    const float* ln_beta     = (const float*)d_in[13];
    float* out = (float*)d_out;

    const int B  = in_sizes[0] / D_DIM;
    const int T  = out_size / (B * D_DIM);
    const int BD = B * D_DIM;

    // ALL device-symbol pointers via cudaGetSymbolAddress
    __half *zfh, *zfnh, *zsAh, *zsBh;
    float *gif, *gis, *zsA, *zsB;
    cudaGetSymbolAddress((void**)&zfh,  g_zfh);
    cudaGetSymbolAddress((void**)&gif,  g_gif);
    cudaGetSymbolAddress((void**)&gis,  g_gis);
    cudaGetSymbolAddress((void**)&zfnh, g_zfnh);
    cudaGetSymbolAddress((void**)&zsA,  g_zs0);
    cudaGetSymbolAddress((void**)&zsAh, g_zs0h);
    cudaGetSymbolAddress((void**)&zsB,  g_zs1);
    cudaGetSymbolAddress((void**)&zsBh, g_zs1h);
    float*  zs[2]  = { zsA, zsB };
    __half* zsh[2] = { zsAh, zsBh };

    cudaFuncSetAttribute(hidden_gemm, cudaFuncAttributeMaxDynamicSharedMemorySize, HID_SMEM);
    cudaFuncSetAttribute(gate_gemm,   cudaFuncAttributeMaxDynamicSharedMemorySize, GATE_SMEM);

    // prologue
    prep<<<dim3(3 * D_DIM, 6), 256>>>(z_init, step_embeds,
                                      fast_w_ih, fast_b_ih, slow_w_ih, slow_b_ih,
                                      fast_w_hh, slow_w_hh, gate_w, B, T);

    const int ewBlocks = (BD / 4 + 255) / 256;
    const int MT = B / 128;      // 16 row tiles

    int cur = 0;
    for (int t = 0; t < T; t++) {
        const bool even = ((t & 1) == 0);

        // hidden GEMMs: fast (12 col tiles) + slow slice (balanced across steps)
        int nslow, sbase;
        if (t == 0)      { nslow = 12; sbase = 0; }
        else if (!even)  { nslow = (t + 1 < T) ? 6 : 0; sbase = 0; }
        else             { nslow = 6;  sbase = 6; }

        {
            dim3 grid(MT, 12 + nslow, 1);
            hidden_gemm<<<grid, 256, HID_SMEM>>>(zfh, zsh[cur], sbase);
        }

        // GRU elementwise (fast + slow on even steps)
        const int ncur = even ? (cur ^ 1) : cur;
        {
            dim3 grid(ewBlocks, 1, even ? 2 : 1);
            gru_ew2<<<grid, 256>>>(gif + (size_t)t * 3 * D_DIM, gis + (size_t)t * 3 * D_DIM,
                                   fast_b_hh, slow_b_hh,
                                   zs[cur], zs[ncur], zsh[ncur], BD);
        }

        // gate GEMM: zfn-half every step; zs-half only when zs changed (even steps)
        {
            dim3 grid(B / 64, D_DIM / 64, even ? 2 : 1);
            gate_gemm<<<grid, 256, GATE_SMEM>>>(zfnh, zsh[ncur]);
        }

        // fuse + residual + LN (sums gpre0 + gpre1)
        gate_fuse_ln<<<B, 128>>>(gate_b, zs[ncur], ln_gamma, ln_beta, out, t, T);

        cur = ncur;
    }
}

// round 12
// speedup vs baseline: 1.2444x; 1.0131x over previous
#include <cuda_runtime.h>
#include <cuda_fp16.h>
#include <cstdint>

#define D_DIM 512
#define B_MAX 2048
#define T_CAP 64

// ---------------- device scratch ----------------
__device__ __half g_wfh[3 * D_DIM * D_DIM];
__device__ __half g_wsh[3 * D_DIM * D_DIM];
__device__ __half g_wgh[D_DIM * 2 * D_DIM];
__device__ float  g_gif[T_CAP * 3 * D_DIM];
__device__ float  g_gis[T_CAP * 3 * D_DIM];
__device__ float  g_zf  [B_MAX * D_DIM];
__device__ __half g_zfh [B_MAX * D_DIM];
__device__ float  g_zfn [B_MAX * D_DIM];
__device__ __half g_zfnh[B_MAX * D_DIM];
__device__ float  g_zs0 [B_MAX * D_DIM];
__device__ __half g_zs0h[B_MAX * D_DIM];
__device__ float  g_zs1 [B_MAX * D_DIM];
__device__ __half g_zs1h[B_MAX * D_DIM];
__device__ float  g_ghf[B_MAX * 3 * D_DIM];
__device__ float  g_ghs[B_MAX * 3 * D_DIM];
__device__ float  g_gpre0[B_MAX * D_DIM];
__device__ float  g_gpre1[B_MAX * D_DIM];

// ---------------- helpers ----------------
__device__ __forceinline__ float sigm(float x) { return 1.0f / (1.0f + __expf(-x)); }

__device__ __forceinline__ void mma16(float* c, const uint32_t* a, uint32_t b0, uint32_t b1) {
    asm volatile(
        "mma.sync.aligned.m16n8k16.row.col.f32.f16.f16.f32 "
        "{%0,%1,%2,%3}, {%4,%5,%6,%7}, {%8,%9}, {%0,%1,%2,%3};\n"
        : "+f"(c[0]), "+f"(c[1]), "+f"(c[2]), "+f"(c[3])
        : "r"(a[0]), "r"(a[1]), "r"(a[2]), "r"(a[3]), "r"(b0), "r"(b1));
}

__device__ __forceinline__ void cp16(void* s, const void* g) {
    uint32_t sa = (uint32_t)__cvta_generic_to_shared(s);
    asm volatile("cp.async.cg.shared.global [%0], [%1], 16;\n" :: "r"(sa), "l"(g));
}

__device__ __forceinline__ void ldsm_x4(uint32_t& r0, uint32_t& r1, uint32_t& r2, uint32_t& r3,
                                        uint32_t addr) {
    asm volatile("ldmatrix.sync.aligned.m8n8.x4.shared.b16 {%0,%1,%2,%3}, [%4];"
                 : "=r"(r0), "=r"(r1), "=r"(r2), "=r"(r3) : "r"(addr));
}

// ---------------- fp16 GEMM core: C[tile] = A @ W^T, fp32 accum ----------------
// 3-stage cp.async ring, ONE __syncthreads per K-chunk, register double-buffered
// fragments (next k16's A / next B pair ldsm'd before current MMAs consume).
#define KC  64
#define NST 3
#define SSTRH 72

template<int TM_, int TN_>
__device__ __forceinline__ void gemm_core(
    __half* hsm,
    const __half* __restrict__ A, int lda,
    const __half* __restrict__ W, int ldw,
    float* __restrict__ C, int ldc, int K, int rowBase, int colBase)
{
    constexpr int A_STAGE = TM_ * SSTRH;
    constexpr int B_STAGE = TN_ * SSTRH;
    constexpr int MW  = (TM_ == 128) ? 4 : 2;       // warps along m
    constexpr int NJ  = TN_ * MW / 64;              // n8-tiles per warp
    constexpr int NJ2 = NJ / 2;                     // B ldsm.x4 per k16
    constexpr int KC16 = KC / 16;                   // 4

    __half* As = hsm;
    __half* Bs = hsm + NST * A_STAGE;
    const uint32_t a_u32 = (uint32_t)__cvta_generic_to_shared(As);
    const uint32_t b_u32 = (uint32_t)__cvta_generic_to_shared(Bs);

    const int tid = threadIdx.x, warp = tid >> 5, lane = tid & 31;
    const int wm0 = (warp % MW) * 32;
    const int wn0 = (warp / MW) * (NJ * 8);
    const int group = lane >> 2, tid4 = lane & 3;

    const int arow = lane & 15, akofs = (lane >> 4) * 8;
    const uint32_t aoff0 = a_u32 + (uint32_t)(((wm0 + arow) * SSTRH + akofs) * 2);
    const int bw = (lane & 7) + ((lane >> 4) & 1) * 8;
    const int bk = ((lane >> 3) & 1) * 8;
    const uint32_t boff0 = b_u32 + (uint32_t)(((wn0 + bw) * SSTRH + bk) * 2);

    float acc[2][NJ][4];
#pragma unroll
    for (int i = 0; i < 2; i++)
#pragma unroll
        for (int j = 0; j < NJ; j++)
#pragma unroll
            for (int k = 0; k < 4; k++) acc[i][j][k] = 0.0f;

    auto issue = [&](int ic, int buf) {
        const int kk = ic * KC;
        __half* as = As + buf * A_STAGE;
        __half* bs = Bs + buf * B_STAGE;
#pragma unroll
        for (int t = 0; t < TM_ / 32; t++) {
            const int seg = tid + t * 256;
            const int r = seg >> 3, c = (seg & 7) * 8;
            cp16(as + r * SSTRH + c, A + (size_t)(rowBase + r) * lda + kk + c);
        }
#pragma unroll
        for (int t = 0; t < TN_ / 32; t++) {
            const int seg = tid + t * 256;
            const int r = seg >> 3, c = (seg & 7) * 8;
            cp16(bs + r * SSTRH + c, W + (size_t)(colBase + r) * ldw + kk + c);
        }
        asm volatile("cp.async.commit_group;\n" ::);
    };

    const int NK = K / KC;
    issue(0, 0);
    if (NK > 1) issue(1, 1);

    for (int ic = 0; ic < NK; ic++) {
        const int buf = ic % NST;
        if (ic + 1 < NK) {
            asm volatile("cp.async.wait_group 1;\n" ::);
        } else {
            asm volatile("cp.async.wait_group 0;\n" ::);
        }
        __syncthreads();   // single barrier per chunk (ring depth 3)

        const uint32_t abuf = (uint32_t)(buf * A_STAGE * 2);
        const uint32_t bbuf = (uint32_t)(buf * B_STAGE * 2);

        uint32_t a[2][2][4];
        uint32_t bb[2][4];

        ldsm_x4(a[0][0][0], a[0][0][1], a[0][0][2], a[0][0][3], aoff0 + abuf);
        ldsm_x4(a[0][1][0], a[0][1][1], a[0][1][2], a[0][1][3],
                aoff0 + abuf + (uint32_t)(16 * SSTRH * 2));
        ldsm_x4(bb[0][0], bb[0][1], bb[0][2], bb[0][3], boff0 + bbuf);

#pragma unroll
        for (int k16 = 0; k16 < KC16; k16++) {
            const uint32_t kb = (uint32_t)(k16 * 32);
            if (k16 + 1 < KC16) {
                const int pa = (k16 + 1) & 1;
                ldsm_x4(a[pa][0][0], a[pa][0][1], a[pa][0][2], a[pa][0][3],
                        aoff0 + abuf + kb + 32u);
                ldsm_x4(a[pa][1][0], a[pa][1][1], a[pa][1][2], a[pa][1][3],
                        aoff0 + abuf + kb + 32u + (uint32_t)(16 * SSTRH * 2));
            }
#pragma unroll
            for (int jj = 0; jj < NJ2; jj++) {
                const int g = k16 * NJ2 + jj;
                if (g + 1 < KC16 * NJ2) {
                    const int nj = (jj + 1 < NJ2) ? jj + 1 : 0;
                    const uint32_t nkb = (jj + 1 < NJ2) ? kb : kb + 32u;
                    const int pb = (g + 1) & 1;
                    ldsm_x4(bb[pb][0], bb[pb][1], bb[pb][2], bb[pb][3],
                            boff0 + bbuf + nkb + (uint32_t)(nj * 16 * SSTRH * 2));
                }
                const uint32_t* av0 = a[k16 & 1][0];
                const uint32_t* av1 = a[k16 & 1][1];
                const uint32_t* bv  = bb[g & 1];
                mma16(acc[0][2 * jj],     av0, bv[0], bv[1]);
                mma16(acc[1][2 * jj],     av1, bv[0], bv[1]);
                mma16(acc[0][2 * jj + 1], av0, bv[2], bv[3]);
                mma16(acc[1][2 * jj + 1], av1, bv[2], bv[3]);
            }
        }
        if (ic + 2 < NK) issue(ic + 2, (ic + 2) % NST);
    }

#pragma unroll
    for (int i = 0; i < 2; i++) {
        const int r0 = rowBase + wm0 + i * 16 + group;
#pragma unroll
        for (int j = 0; j < NJ; j++) {
            const int c0 = colBase + wn0 + j * 8 + tid4 * 2;
            *(float2*)&C[(size_t)r0 * ldc + c0]       = make_float2(acc[i][j][0], acc[i][j][1]);
            *(float2*)&C[(size_t)(r0 + 8) * ldc + c0] = make_float2(acc[i][j][2], acc[i][j][3]);
        }
    }
}

// hidden GEMMs: y<12 -> fast col tiles; y>=12 -> slow col tiles at (y-12+sbase)
#define HID_SMEM ((128 + 128) * SSTRH * 2 * NST)    // 110592 B
__global__ __launch_bounds__(256, 2) void hidden_gemm(
    const __half* __restrict__ zfh, const __half* __restrict__ zsh, int sbase)
{
    extern __shared__ __half hsm[];
    const int y = blockIdx.y;
    const bool fast = (y < 12);
    const __half* Ap = fast ? zfh : zsh;
    const __half* Wp = fast ? g_wfh : g_wsh;
    float*       Cp  = fast ? g_ghf : g_ghs;
    const int col = fast ? y : (y - 12 + sbase);
    gemm_core<128, 128>(hsm, Ap, D_DIM, Wp, D_DIM,
                        Cp, 3 * D_DIM, D_DIM, blockIdx.x * 128, col * 128);
}

// gate GEMM halves, 128x128 tiles (same efficient shape as hidden):
// z=0 -> zfn @ Wg[:, :512] -> gpre0 ; z=1 -> zs @ Wg[:, 512:] -> gpre1
__global__ __launch_bounds__(256, 2) void gate_gemm(
    const __half* __restrict__ zfnh, const __half* __restrict__ zsnh)
{
    extern __shared__ __half hsm[];
    const int z = blockIdx.z;
    const __half* Ap = z ? zsnh : zfnh;
    const __half* Wp = g_wgh + (z ? D_DIM : 0);
    float*       Cp  = z ? g_gpre1 : g_gpre0;
    gemm_core<128, 128>(hsm, Ap, D_DIM, Wp, 2 * D_DIM,
                        Cp, D_DIM, D_DIM, blockIdx.x * 128, blockIdx.y * 128);
}

// ---------------- GRU elementwise (fast + optional slow via blockIdx.z) ----------------
__global__ void gru_ew2(const float* __restrict__ gif_t, const float* __restrict__ gis_t,
                        const float* __restrict__ fbhh, const float* __restrict__ sbhh,
                        const float* __restrict__ zsc,
                        float* __restrict__ zsn, __half* __restrict__ zsnh, int BD)
{
    const int slow = blockIdx.z;
    const float* gh  = slow ? g_ghs : g_ghf;
    const float* gi  = slow ? gis_t : gif_t;
    const float* bhh = slow ? sbhh : fbhh;
    const float* h   = slow ? zsc : g_zf;
    float*  ho  = slow ? zsn : g_zfn;
    __half* hoh = slow ? zsnh : g_zfnh;

    int i = (blockIdx.x * blockDim.x + threadIdx.x) * 4;
    if (i >= BD) return;
    const int b = i >> 9;
    const int j = i & (D_DIM - 1);
    const size_t base = (size_t)b * (3 * D_DIM) + j;

    float4 gA = *(const float4*)(gh + base);
    float4 gB = *(const float4*)(gh + base + D_DIM);
    float4 gC = *(const float4*)(gh + base + 2 * D_DIM);
    float4 iA = *(const float4*)(gi + j);
    float4 iB = *(const float4*)(gi + j + D_DIM);
    float4 iC = *(const float4*)(gi + j + 2 * D_DIM);
    float4 bA = *(const float4*)(bhh + j);
    float4 bB = *(const float4*)(bhh + j + D_DIM);
    float4 bC = *(const float4*)(bhh + j + 2 * D_DIM);
    float4 hv = *(const float4*)(h + i);

    float4 o;
    { float r = sigm(iA.x + gA.x + bA.x); float z = sigm(iB.x + gB.x + bB.x);
      float n = tanhf(iC.x + r * (gC.x + bC.x)); o.x = n + z * (hv.x - n); }
    { float r = sigm(iA.y + gA.y + bA.y); float z = sigm(iB.y + gB.y + bB.y);
      float n = tanhf(iC.y + r * (gC.y + bC.y)); o.y = n + z * (hv.y - n); }
    { float r = sigm(iA.z + gA.z + bA.z); float z = sigm(iB.z + gB.z + bB.z);
      float n = tanhf(iC.z + r * (gC.z + bC.z)); o.z = n + z * (hv.z - n); }
    { float r = sigm(iA.w + gA.w + bA.w); float z = sigm(iB.w + gB.w + bB.w);
      float n = tanhf(iC.w + r * (gC.w + bC.w)); o.w = n + z * (hv.w - n); }

    *(float4*)(ho + i) = o;
    *(__half2*)(hoh + i)     = make_half2(__float2half_rn(o.x), __float2half_rn(o.y));
    *(__half2*)(hoh + i + 2) = make_half2(__float2half_rn(o.z), __float2half_rn(o.w));
}

// ---------------- gate + fuse + residual + LayerNorm ----------------
__device__ __forceinline__ float block_sum_128(float v, float* red, int tid) {
#pragma unroll
    for (int o = 16; o > 0; o >>= 1) v += __shfl_xor_sync(0xffffffffu, v, o);
    if ((tid & 31) == 0) red[tid >> 5] = v;
    __syncthreads();
    v = red[0] + red[1] + red[2] + red[3];
    __syncthreads();
    return v;
}

__global__ void gate_fuse_ln(const float* __restrict__ gateb,
                             const float* __restrict__ zs,
                             const float* __restrict__ gamma, const float* __restrict__ beta,
                             float* __restrict__ out, int t, int T)
{
    __shared__ float red[4];
    const int b = blockIdx.x, tid = threadIdx.x;
    const int j = tid * 4;
    const size_t base = (size_t)b * D_DIM + j;

    float4 p0 = *(const float4*)(g_gpre0 + base);
    float4 p1 = *(const float4*)(g_gpre1 + base);   // zs-half: stale on odd steps == correct
    float4 gb = *(const float4*)(gateb + j);
    float4 a  = *(const float4*)(g_zfn + base);
    float4 s  = *(const float4*)(zs + base);
    float4 ho = *(const float4*)(g_zf + base);

    float f[4];
    { float g = sigm(p0.x + p1.x + gb.x); f[0] = s.x + g * (a.x - s.x) + ho.x; }
    { float g = sigm(p0.y + p1.y + gb.y); f[1] = s.y + g * (a.y - s.y) + ho.y; }
    { float g = sigm(p0.z + p1.z + gb.z); f[2] = s.z + g * (a.z - s.z) + ho.z; }
    { float g = sigm(p0.w + p1.w + gb.w); f[3] = s.w + g * (a.w - s.w) + ho.w; }

    float sum = f[0] + f[1] + f[2] + f[3];
    sum = block_sum_128(sum, red, tid);
    const float mu = sum * (1.0f / D_DIM);

    float sq = 0.0f;
#pragma unroll
    for (int k = 0; k < 4; k++) { float d = f[k] - mu; sq += d * d; }
    sq = block_sum_128(sq, red, tid);
    const float rstd = rsqrtf(sq * (1.0f / D_DIM) + 1e-5f);

    float4 gm = *(const float4*)(gamma + j);
    float4 bt = *(const float4*)(beta + j);
    float4 y;
    y.x = (f[0] - mu) * rstd * gm.x + bt.x;
    y.y = (f[1] - mu) * rstd * gm.y + bt.y;
    y.z = (f[2] - mu) * rstd * gm.z + bt.z;
    y.w = (f[3] - mu) * rstd * gm.w + bt.w;

    *(float4*)(out + ((size_t)b * T + t) * D_DIM + j) = y;
    *(float4*)(g_zf + base) = y;
    *(__half2*)(g_zfh + base)     = make_half2(__float2half_rn(y.x), __float2half_rn(y.y));
    *(__half2*)(g_zfh + base + 2) = make_half2(__float2half_rn(y.z), __float2half_rn(y.w));
}

// ---------------- fused prologue ----------------
__global__ void prep(const float* __restrict__ z_init,
                     const float* __restrict__ emb,
                     const float* __restrict__ fwih, const float* __restrict__ fbih,
                     const float* __restrict__ swih, const float* __restrict__ sbih,
                     const float* __restrict__ fwhh, const float* __restrict__ swhh,
                     const float* __restrict__ gatew,
                     int B, int T)
{
    const int y = blockIdx.y;
    const int tid = threadIdx.x;
    const int BD = B * D_DIM;

    if (y < 3) {
        const float* src = (y == 0) ? fwhh : (y == 1) ? swhh : gatew;
        __half* dst = (y == 0) ? g_wfh : (y == 1) ? g_wsh : g_wgh;
        const int n = (y == 2) ? (D_DIM * 2 * D_DIM) : (3 * D_DIM * D_DIM);
        for (int i = (blockIdx.x * 256 + tid) * 4; i < n; i += gridDim.x * 256 * 4) {
            float4 v = *(const float4*)(src + i);
            *(__half2*)(dst + i)     = make_half2(__float2half_rn(v.x), __float2half_rn(v.y));
            *(__half2*)(dst + i + 2) = make_half2(__float2half_rn(v.z), __float2half_rn(v.w));
        }
    } else if (y == 3) {
        for (int i = (blockIdx.x * 256 + tid) * 4; i < BD; i += gridDim.x * 256 * 4) {
            float4 v = *(const float4*)(z_init + i);
            *(float4*)(g_zf + i)  = v;
            *(float4*)(g_zs0 + i) = v;
            __half2 h01 = make_half2(__float2half_rn(v.x), __float2half_rn(v.y));
            __half2 h23 = make_half2(__float2half_rn(v.z), __float2half_rn(v.w));
            *(__half2*)(g_zfh + i)      = h01;
            *(__half2*)(g_zfh + i + 2)  = h23;
            *(__half2*)(g_zs0h + i)     = h01;
            *(__half2*)(g_zs0h + i + 2) = h23;
        }
    } else {
        const int m = blockIdx.x;
        if (m >= 3 * D_DIM || tid >= T) return;
        const float* wih = (y == 4) ? fwih : swih;
        const float* bih = (y == 4) ? fbih : sbih;
        float* gi = (y == 4) ? g_gif : g_gis;
        const float4* wr = (const float4*)(wih + (size_t)m * D_DIM);
        const float4* er = (const float4*)(emb + (size_t)tid * D_DIM);
        float s = 0.0f;
        for (int k = 0; k < D_DIM / 4; k++) {
            float4 w = wr[k], e = er[k];
            s += w.x * e.x + w.y * e.y + w.z * e.z + w.w * e.w;
        }
        gi[(size_t)tid * (3 * D_DIM) + m] = s + bih[m];
    }
}

// ---------------- host driver ----------------
extern "C" void kernel_launch(void* const* d_in, const int* in_sizes, int n_in,
                              void* d_out, int out_size)
{
    const float* z_init      = (const float*)d_in[0];
    const float* step_embeds = (const float*)d_in[1];
    const float* fast_w_ih   = (const float*)d_in[2];
    const float* fast_w_hh   = (const float*)d_in[3];
    const float* fast_b_ih   = (const float*)d_in[4];
    const float* fast_b_hh   = (const float*)d_in[5];
    const float* slow_w_ih   = (const float*)d_in[6];
    const float* slow_w_hh   = (const float*)d_in[7];
    const float* slow_b_ih   = (const float*)d_in[8];
    const float* slow_b_hh   = (const float*)d_in[9];
    const float* gate_w      = (const float*)d_in[10];
    const float* gate_b      = (const float*)d_in[11];
    const float* ln_gamma    = (const float*)d_in[12];
    const float* ln_beta     = (const float*)d_in[13];
    float* out = (float*)d_out;

    const int B  = in_sizes[0] / D_DIM;
    const int T  = out_size / (B * D_DIM);
    const int BD = B * D_DIM;

    __half *zfh, *zfnh, *zsAh, *zsBh;
    float *gif, *gis, *zsA, *zsB;
    cudaGetSymbolAddress((void**)&zfh,  g_zfh);
    cudaGetSymbolAddress((void**)&gif,  g_gif);
    cudaGetSymbolAddress((void**)&gis,  g_gis);
    cudaGetSymbolAddress((void**)&zfnh, g_zfnh);
    cudaGetSymbolAddress((void**)&zsA,  g_zs0);
    cudaGetSymbolAddress((void**)&zsAh, g_zs0h);
    cudaGetSymbolAddress((void**)&zsB,  g_zs1);
    cudaGetSymbolAddress((void**)&zsBh, g_zs1h);
    float*  zs[2]  = { zsA, zsB };
    __half* zsh[2] = { zsAh, zsBh };

    cudaFuncSetAttribute(hidden_gemm, cudaFuncAttributeMaxDynamicSharedMemorySize, HID_SMEM);
    cudaFuncSetAttribute(gate_gemm,   cudaFuncAttributeMaxDynamicSharedMemorySize, HID_SMEM);

    // prologue
    prep<<<dim3(3 * D_DIM, 6), 256>>>(z_init, step_embeds,
                                      fast_w_ih, fast_b_ih, slow_w_ih, slow_b_ih,
                                      fast_w_hh, slow_w_hh, gate_w, B, T);

    const int ewBlocks = (BD / 4 + 255) / 256;
    const int MT = B / 128;      // 16 row tiles

    int cur = 0;
    for (int t = 0; t < T; t++) {
        const bool even = ((t & 1) == 0);

        // hidden GEMMs: fast (12 col tiles) + slow slice (balanced across steps)
        int nslow, sbase;
        if (t == 0)      { nslow = 12; sbase = 0; }
        else if (!even)  { nslow = (t + 1 < T) ? 6 : 0; sbase = 0; }
        else             { nslow = 6;  sbase = 6; }

        {
            dim3 grid(MT, 12 + nslow, 1);
            hidden_gemm<<<grid, 256, HID_SMEM>>>(zfh, zsh[cur], sbase);
        }

        // GRU elementwise (fast + slow on even steps)
        const int ncur = even ? (cur ^ 1) : cur;
        {
            dim3 grid(ewBlocks, 1, even ? 2 : 1);
            gru_ew2<<<grid, 256>>>(gif + (size_t)t * 3 * D_DIM, gis + (size_t)t * 3 * D_DIM,
                                   fast_b_hh, slow_b_hh,
                                   zs[cur], zs[ncur], zsh[ncur], BD);
        }

        // gate GEMM: 128x128 tiles; zfn-half every step, zs-half on even steps only
        {
            dim3 grid(MT, D_DIM / 128, even ? 2 : 1);
            gate_gemm<<<grid, 256, HID_SMEM>>>(zfnh, zsh[ncur]);
        }

        // fuse + residual + LN (sums gpre0 + gpre1)
        gate_fuse_ln<<<B, 128>>>(gate_b, zs[ncur], ln_gamma, ln_beta, out, t, T);

        cur = ncur;
    }
}